// round 2
// baseline (speedup 1.0000x reference)
#include <cuda_runtime.h>
#include <math.h>

#define BB   64
#define TT   1024
#define HH   512
#define G4   2048        // 4*H
#define MTOT (BB * TT)   // 65536

// ---- static device scratch (no allocation allowed) ----
__device__ float g_xg[(size_t)MTOT * G4];     // 512 MB: per-layer input projection
__device__ float g_bufA[(size_t)MTOT * HH];   // 128 MB: layer 0 output
__device__ float g_bufB[(size_t)MTOT * HH];   // 128 MB: layer 1 output
__device__ float g_hbuf[2][BB * HH];          // ping-pong hidden state
__device__ unsigned g_cnt = 0;                // grid barrier arrive counter
__device__ unsigned g_gen = 0;                // grid barrier generation

// ============================================================
// Big input-projection GEMM: g_xg[m, n] = sum_k X[m,k]*W[n,k] + bih[n]+bhh[n]
// M=65536, N=2048, K=512. Tiles: 128x128x16, 256 threads, 8x8 per thread.
// ============================================================
__global__ __launch_bounds__(256) void xg_gemm(const float* __restrict__ X,
                                               const float* __restrict__ W,
                                               const float* __restrict__ bih,
                                               const float* __restrict__ bhh)
{
    __shared__ float As[16][128];   // [k][m]
    __shared__ float Bs[16][128];   // [k][n]
    const int tid   = threadIdx.x;
    const int m_blk = blockIdx.x * 128;
    const int n_blk = blockIdx.y * 128;
    const int lr = tid >> 1;
    const int lh = (tid & 1) << 3;
    const float* Aptr = X + (size_t)(m_blk + lr) * HH + lh;
    const float* Bptr = W + (size_t)(n_blk + lr) * HH + lh;
    const int ty = tid >> 4;
    const int tx = tid & 15;

    float acc[8][8];
#pragma unroll
    for (int i = 0; i < 8; i++)
#pragma unroll
        for (int j = 0; j < 8; j++) acc[i][j] = 0.f;

    for (int k0 = 0; k0 < HH; k0 += 16) {
        float4 a0 = *(const float4*)(Aptr + k0);
        float4 a1 = *(const float4*)(Aptr + k0 + 4);
        float4 b0 = *(const float4*)(Bptr + k0);
        float4 b1 = *(const float4*)(Bptr + k0 + 4);
        __syncthreads();
        As[lh+0][lr]=a0.x; As[lh+1][lr]=a0.y; As[lh+2][lr]=a0.z; As[lh+3][lr]=a0.w;
        As[lh+4][lr]=a1.x; As[lh+5][lr]=a1.y; As[lh+6][lr]=a1.z; As[lh+7][lr]=a1.w;
        Bs[lh+0][lr]=b0.x; Bs[lh+1][lr]=b0.y; Bs[lh+2][lr]=b0.z; Bs[lh+3][lr]=b0.w;
        Bs[lh+4][lr]=b1.x; Bs[lh+5][lr]=b1.y; Bs[lh+6][lr]=b1.z; Bs[lh+7][lr]=b1.w;
        __syncthreads();
#pragma unroll
        for (int k = 0; k < 16; k++) {
            float4 av0 = *(const float4*)&As[k][ty << 3];
            float4 av1 = *(const float4*)&As[k][(ty << 3) + 4];
            float4 bv0 = *(const float4*)&Bs[k][tx << 3];
            float4 bv1 = *(const float4*)&Bs[k][(tx << 3) + 4];
            float av[8] = {av0.x,av0.y,av0.z,av0.w,av1.x,av1.y,av1.z,av1.w};
            float bv[8] = {bv0.x,bv0.y,bv0.z,bv0.w,bv1.x,bv1.y,bv1.z,bv1.w};
#pragma unroll
            for (int i = 0; i < 8; i++)
#pragma unroll
                for (int j = 0; j < 8; j++)
                    acc[i][j] += av[i] * bv[j];
        }
    }

    float bsum[8];
#pragma unroll
    for (int j = 0; j < 8; j++) {
        int n = n_blk + (tx << 3) + j;
        bsum[j] = bih[n] + bhh[n];
    }
#pragma unroll
    for (int i = 0; i < 8; i++) {
        size_t m = (size_t)m_blk + (ty << 3) + i;
        float* orow = g_xg + m * G4 + n_blk + (tx << 3);
        float4 v0, v1;
        v0.x = acc[i][0]+bsum[0]; v0.y = acc[i][1]+bsum[1];
        v0.z = acc[i][2]+bsum[2]; v0.w = acc[i][3]+bsum[3];
        v1.x = acc[i][4]+bsum[4]; v1.y = acc[i][5]+bsum[5];
        v1.z = acc[i][6]+bsum[6]; v1.w = acc[i][7]+bsum[7];
        *(float4*)orow       = v0;
        *(float4*)(orow + 4) = v1;
    }
}

// ============================================================
// Persistent recurrence kernel: one launch does all 1024 timesteps.
// Grid: 128 CTAs x 256 threads, ALL co-resident (1 CTA/SM, 176KB smem).
// CTA c: b_base = (c>>5)*16 (batch tile of 16), n_base = (c&31)*16 (hidden
// tile of 16 -> 64 gate columns). Weights stay in smem for all steps.
// Thread (ty=tid>>4, tx=tid&15): batch ty, gate-cols jj = 4*tx..4*tx+3.
// c-state lives in a register of the gate-update thread.
// ============================================================
#define WT_PITCH 68          // 64 jj + 4 pad
#define HS_PITCH 516         // 512 k + 4 pad
#define WT_OFF   0                                   // 512*68  = 34816 floats
#define HS_OFF   (512 * WT_PITCH)                    // 16*516  =  8256 floats
#define GA_OFF   (HS_OFF + 16 * HS_PITCH)            // 16*68   =  1088 floats
#define SMEM_FLOATS (GA_OFF + 16 * WT_PITCH)
#define NCTA 128

__device__ __forceinline__ void grid_sync()
{
    __syncthreads();
    if (threadIdx.x == 0) {
        __threadfence();
        unsigned my = *(volatile unsigned*)&g_gen;
        if (atomicAdd(&g_cnt, 1) == NCTA - 1) {
            atomicExch(&g_cnt, 0);
            __threadfence();
            atomicAdd(&g_gen, 1);
        } else {
            while (*(volatile unsigned*)&g_gen == my) { __nanosleep(64); }
        }
    }
    __syncthreads();
}

__global__ __launch_bounds__(256, 1) void rec_persist(const float* __restrict__ Whh,
                                                      float* __restrict__ out)
{
    extern __shared__ float sm[];
    float* wt   = sm + WT_OFF;   // wt[k][jj], pitch 68
    float* h_s  = sm + HS_OFF;   // h_s[b][k], pitch 516
    float* gacc = sm + GA_OFF;   // gacc[b][jj], pitch 68

    const int tid    = threadIdx.x;
    const int cta    = blockIdx.x;
    const int b_base = (cta >> 5) << 4;
    const int n_base = (cta & 31) << 4;

    // ---- load (transposed) weight tile once: 64 cols x 512 k = 128 KB ----
    for (int idx = tid; idx < 64 * 512; idx += 256) {
        int jj = idx >> 9;
        int k  = idx & 511;
        int jglob = ((jj >> 4) << 9) + n_base + (jj & 15);   // gate*512 + n
        wt[k * WT_PITCH + jj] = Whh[(size_t)jglob * HH + k];
    }

    // ---- zero initial h buffer (buffer 0): 32768 floats over 128 CTAs ----
    {
        int i = cta * 256 + tid;
        g_hbuf[0][i] = 0.f;
    }

    // ---- per-thread state for gate-update role ----
    const int ub = tid >> 4;          // 0..15 local batch
    const int un = tid & 15;          // 0..15 local hidden
    const int b_glob = b_base + ub;
    float c_reg = 0.f;

    // compute-role indices
    const int ty  = tid >> 4;         // local batch for GEMM
    const int jj0 = (tid & 15) << 2;  // 4 gate-cols

    grid_sync();                      // h zeros + (local) weights visible

    int cur = 0;
    for (int t = 0; t < TT; t++) {
        // ---- stage h tile [16 x 512] into smem ----
        const float* hc = g_hbuf[cur] + (size_t)b_base * HH;
        for (int idx = tid; idx < 16 * 128; idx += 256) {
            int b  = idx >> 7;
            int k4 = idx & 127;
            float4 v = *(const float4*)(hc + b * HH + (k4 << 2));
            *(float4*)&h_s[b * HS_PITCH + (k4 << 2)] = v;
        }
        __syncthreads();

        // ---- GEMM: acc[q] = sum_k h[ty][k] * wt[k][jj0+q] ----
        float a0 = 0.f, a1 = 0.f, a2 = 0.f, a3 = 0.f;
        const float* hrow = &h_s[ty * HS_PITCH];
#pragma unroll 8
        for (int k = 0; k < 512; k++) {
            float hv = hrow[k];
            float4 wv = *(const float4*)&wt[k * WT_PITCH + jj0];
            a0 += hv * wv.x;
            a1 += hv * wv.y;
            a2 += hv * wv.z;
            a3 += hv * wv.w;
        }
        float4 av; av.x = a0; av.y = a1; av.z = a2; av.w = a3;
        *(float4*)&gacc[ty * WT_PITCH + jj0] = av;
        __syncthreads();

        // ---- gate fuse + state update (one (b,n) element per thread) ----
        {
            const float* xr = g_xg + ((size_t)b_glob * TT + t) * G4 + n_base + un;
            float gi = gacc[ub * WT_PITCH +  0 + un] + xr[0];
            float gf = gacc[ub * WT_PITCH + 16 + un] + xr[512];
            float gg = gacc[ub * WT_PITCH + 32 + un] + xr[1024];
            float go = gacc[ub * WT_PITCH + 48 + un] + xr[1536];

            float si = 1.f / (1.f + __expf(-gi));
            float sf = 1.f / (1.f + __expf(-gf));
            float so = 1.f / (1.f + __expf(-go));
            float cn = sf * c_reg + si * tanhf(gg);
            float hn = so * tanhf(cn);
            c_reg = cn;

            g_hbuf[cur ^ 1][b_glob * HH + n_base + un] = hn;
            out[((size_t)b_glob * TT + t) * HH + n_base + un] = hn;
        }

        grid_sync();     // all h writes visible before next step's staging
        cur ^= 1;
    }
}

// ============================================================
// Host launcher: 6 graph nodes total.
// ============================================================
extern "C" void kernel_launch(void* const* d_in, const int* in_sizes, int n_in,
                              void* d_out, int out_size)
{
    const float* x    = (const float*)d_in[0];
    const float* w_ih = (const float*)d_in[1];
    const float* w_hh = (const float*)d_in[2];
    const float* b_ih = (const float*)d_in[3];
    const float* b_hh = (const float*)d_in[4];
    float* out = (float*)d_out;

    float *bufA = nullptr, *bufB = nullptr;
    cudaGetSymbolAddress((void**)&bufA, g_bufA);
    cudaGetSymbolAddress((void**)&bufB, g_bufB);

    static bool attr_set = false;
    if (!attr_set) {
        cudaFuncSetAttribute(rec_persist,
                             cudaFuncAttributeMaxDynamicSharedMemorySize,
                             SMEM_FLOATS * sizeof(float));
        attr_set = true;
    }

    dim3 ggrid(512, 16);  // M/128, N/128
    for (int l = 0; l < 3; l++) {
        const float* in  = (l == 0) ? x    : (l == 1 ? bufA : bufB);
        float*       lo  = (l == 0) ? bufA : (l == 1 ? bufB : out);
        const float* Wih = w_ih + (size_t)l * G4 * HH;
        const float* Whh = w_hh + (size_t)l * G4 * HH;

        xg_gemm<<<ggrid, 256>>>(in, Wih, b_ih + l * G4, b_hh + l * G4);
        rec_persist<<<NCTA, 256, SMEM_FLOATS * sizeof(float)>>>(Whh, lo);
    }
}

// round 3
// speedup vs baseline: 1.5458x; 1.5458x over previous
#include <cuda_runtime.h>
#include <math.h>

#define BB   64
#define TT   1024
#define HH   512
#define G4   2048        // 4*H
#define MTOT (BB * TT)   // 65536

// ---- static device scratch (no allocation allowed) ----
__device__ float g_xg[(size_t)MTOT * G4];     // 512 MB: per-layer input projection
__device__ float g_bufA[(size_t)MTOT * HH];   // 128 MB: layer 0 output
__device__ float g_bufB[(size_t)MTOT * HH];   // 128 MB: layer 1 output
__device__ float g_hbuf[2][BB * HH];          // ping-pong hidden state
__device__ unsigned g_cnt = 0;                // grid barrier arrive counter
__device__ unsigned g_gen = 0;                // grid barrier generation

// ============================================================
// Big input-projection GEMM: g_xg[m, n] = sum_k X[m,k]*W[n,k] + bih[n]+bhh[n]
// M=65536, N=2048, K=512. Tiles: 128x128x16, 256 threads, 8x8 per thread.
// ============================================================
__global__ __launch_bounds__(256) void xg_gemm(const float* __restrict__ X,
                                               const float* __restrict__ W,
                                               const float* __restrict__ bih,
                                               const float* __restrict__ bhh)
{
    __shared__ float As[16][128];   // [k][m]
    __shared__ float Bs[16][128];   // [k][n]
    const int tid   = threadIdx.x;
    const int m_blk = blockIdx.x * 128;
    const int n_blk = blockIdx.y * 128;
    const int lr = tid >> 1;
    const int lh = (tid & 1) << 3;
    const float* Aptr = X + (size_t)(m_blk + lr) * HH + lh;
    const float* Bptr = W + (size_t)(n_blk + lr) * HH + lh;
    const int ty = tid >> 4;
    const int tx = tid & 15;

    float acc[8][8];
#pragma unroll
    for (int i = 0; i < 8; i++)
#pragma unroll
        for (int j = 0; j < 8; j++) acc[i][j] = 0.f;

    for (int k0 = 0; k0 < HH; k0 += 16) {
        float4 a0 = *(const float4*)(Aptr + k0);
        float4 a1 = *(const float4*)(Aptr + k0 + 4);
        float4 b0 = *(const float4*)(Bptr + k0);
        float4 b1 = *(const float4*)(Bptr + k0 + 4);
        __syncthreads();
        As[lh+0][lr]=a0.x; As[lh+1][lr]=a0.y; As[lh+2][lr]=a0.z; As[lh+3][lr]=a0.w;
        As[lh+4][lr]=a1.x; As[lh+5][lr]=a1.y; As[lh+6][lr]=a1.z; As[lh+7][lr]=a1.w;
        Bs[lh+0][lr]=b0.x; Bs[lh+1][lr]=b0.y; Bs[lh+2][lr]=b0.z; Bs[lh+3][lr]=b0.w;
        Bs[lh+4][lr]=b1.x; Bs[lh+5][lr]=b1.y; Bs[lh+6][lr]=b1.z; Bs[lh+7][lr]=b1.w;
        __syncthreads();
#pragma unroll
        for (int k = 0; k < 16; k++) {
            float4 av0 = *(const float4*)&As[k][ty << 3];
            float4 av1 = *(const float4*)&As[k][(ty << 3) + 4];
            float4 bv0 = *(const float4*)&Bs[k][tx << 3];
            float4 bv1 = *(const float4*)&Bs[k][(tx << 3) + 4];
            float av[8] = {av0.x,av0.y,av0.z,av0.w,av1.x,av1.y,av1.z,av1.w};
            float bv[8] = {bv0.x,bv0.y,bv0.z,bv0.w,bv1.x,bv1.y,bv1.z,bv1.w};
#pragma unroll
            for (int i = 0; i < 8; i++)
#pragma unroll
                for (int j = 0; j < 8; j++)
                    acc[i][j] += av[i] * bv[j];
        }
    }

    float bsum[8];
#pragma unroll
    for (int j = 0; j < 8; j++) {
        int n = n_blk + (tx << 3) + j;
        bsum[j] = bih[n] + bhh[n];
    }
#pragma unroll
    for (int i = 0; i < 8; i++) {
        size_t m = (size_t)m_blk + (ty << 3) + i;
        float* orow = g_xg + m * G4 + n_blk + (tx << 3);
        float4 v0, v1;
        v0.x = acc[i][0]+bsum[0]; v0.y = acc[i][1]+bsum[1];
        v0.z = acc[i][2]+bsum[2]; v0.w = acc[i][3]+bsum[3];
        v1.x = acc[i][4]+bsum[4]; v1.y = acc[i][5]+bsum[5];
        v1.z = acc[i][6]+bsum[6]; v1.w = acc[i][7]+bsum[7];
        *(float4*)orow       = v0;
        *(float4*)(orow + 4) = v1;
    }
}

// ============================================================
// Persistent recurrence kernel: one launch = all 1024 timesteps.
// 128 CTAs x 256 threads, co-resident (1 CTA/SM, ~205KB smem).
// CTA: 16-batch x 16-hidden tile (64 gate cols). Weights resident in smem.
// K split across the 8 warps (64 k each); each lane register-accumulates
// 8 batches x 4 cols; smem reduction; gate fuse; grid barrier.
// ============================================================
#define WTP  68          // wt pitch  (floats)
#define HSP  520         // h_s pitch (floats), avoids bg0/bg1 bank collision
#define NCTA 128

#define WT_OFF   0                               // 512*68  = 34816 floats
#define HS_OFF   (512 * WTP)                     // 16*520  =  8320 floats
#define PW_OFF   (HS_OFF + 16 * HSP)             // 8*256*4 =  8192 floats
#define GA_OFF   (PW_OFF + 8 * 256 * 4)          // 16*68   =  1088 floats
#define SMEM_FLOATS (GA_OFF + 16 * WTP)

__device__ __forceinline__ void grid_sync()
{
    __syncthreads();
    if (threadIdx.x == 0) {
        __threadfence();
        unsigned my = *(volatile unsigned*)&g_gen;
        if (atomicAdd(&g_cnt, 1) == NCTA - 1) {
            atomicExch(&g_cnt, 0);
            __threadfence();
            atomicAdd(&g_gen, 1);
        } else {
            while (*(volatile unsigned*)&g_gen == my) { }
        }
        __threadfence();
    }
    __syncthreads();
}

__global__ __launch_bounds__(256, 1) void rec_persist(const float* __restrict__ Whh,
                                                      float* __restrict__ out)
{
    extern __shared__ float sm[];
    float*  wt   = sm + WT_OFF;                    // wt[k][jj]
    float*  h_s  = sm + HS_OFF;                    // h_s[b][k]
    float4* pw4  = (float4*)(sm + PW_OFF);         // pw4[(w*16+b)*16 + c4]
    float*  gacc = sm + GA_OFF;                    // gacc[b][jj]

    const int tid    = threadIdx.x;
    const int cta    = blockIdx.x;
    const int b_base = (cta >> 5) << 4;
    const int n_base = (cta & 31) << 4;

    // ---- load (transposed) weight tile once: 64 cols x 512 k = 128 KB ----
    for (int idx = tid; idx < 64 * 512; idx += 256) {
        int jj = idx >> 9;
        int k  = idx & 511;
        int jglob = ((jj >> 4) << 9) + n_base + (jj & 15);   // gate*512 + n
        wt[k * WTP + jj] = Whh[(size_t)jglob * HH + k];
    }

    // ---- zero initial h buffer (buffer 0) ----
    g_hbuf[0][cta * 256 + tid] = 0.f;

    // GEMM-role indices
    const int w    = tid >> 5;        // warp id: owns k chunk [w*64, w*64+64)
    const int lane = tid & 31;
    const int c4   = lane & 15;       // float4 col group (4 cols)
    const int bg   = lane >> 4;       // batch group (0: b0..7, 1: b8..15)
    const int kchunk = w << 6;

    // gate-role indices
    const int ub = tid >> 4;          // local batch
    const int un = tid & 15;          // local hidden
    const int b_glob = b_base + ub;
    float c_reg = 0.f;

    // reduce-role indices (thread <-> slot4)
    const int rb  = tid >> 4;
    const int rc4 = tid & 15;

    grid_sync();

    int cur = 0;
    for (int t = 0; t < TT; t++) {
        // ---- prefetch this thread's xg gate pre-activations (global) ----
        const float* xr = g_xg + ((size_t)b_glob * TT + t) * G4 + n_base + un;
        float xgi = __ldg(xr);
        float xgf = __ldg(xr + 512);
        float xgg = __ldg(xr + 1024);
        float xgo = __ldg(xr + 1536);

        // ---- stage h tile [16 x 512] into smem ----
        const float* hc = g_hbuf[cur] + (size_t)b_base * HH;
        for (int idx = tid; idx < 16 * 128; idx += 256) {
            int b  = idx >> 7;
            int k4 = idx & 127;
            float4 v = *(const float4*)(hc + b * HH + (k4 << 2));
            *(float4*)&h_s[b * HSP + (k4 << 2)] = v;
        }
        __syncthreads();

        // ---- GEMM: each warp covers its 64-k chunk for the whole tile ----
        float acc[8][4];
#pragma unroll
        for (int i = 0; i < 8; i++)
#pragma unroll
            for (int j = 0; j < 4; j++) acc[i][j] = 0.f;

        const float* wrow = wt + (size_t)kchunk * WTP + (c4 << 2);
        const float* hrow = h_s + (bg << 3) * HSP + kchunk;
#pragma unroll 4
        for (int kk = 0; kk < 64; kk += 4) {
            float4 wv0 = *(const float4*)(wrow + (kk + 0) * WTP);
            float4 wv1 = *(const float4*)(wrow + (kk + 1) * WTP);
            float4 wv2 = *(const float4*)(wrow + (kk + 2) * WTP);
            float4 wv3 = *(const float4*)(wrow + (kk + 3) * WTP);
#pragma unroll
            for (int i = 0; i < 8; i++) {
                float4 hv = *(const float4*)(hrow + i * HSP + kk);
                acc[i][0] += hv.x * wv0.x + hv.y * wv1.x + hv.z * wv2.x + hv.w * wv3.x;
                acc[i][1] += hv.x * wv0.y + hv.y * wv1.y + hv.z * wv2.y + hv.w * wv3.y;
                acc[i][2] += hv.x * wv0.z + hv.y * wv1.z + hv.z * wv2.z + hv.w * wv3.z;
                acc[i][3] += hv.x * wv0.w + hv.y * wv1.w + hv.z * wv2.w + hv.w * wv3.w;
            }
        }

        // ---- store per-warp partials ----
#pragma unroll
        for (int i = 0; i < 8; i++) {
            float4 v;
            v.x = acc[i][0]; v.y = acc[i][1]; v.z = acc[i][2]; v.w = acc[i][3];
            pw4[((w << 4) + (bg << 3) + i) * 16 + c4] = v;
        }
        __syncthreads();

        // ---- reduce 8 partials -> gacc ----
        {
            float4 s = pw4[(rb) * 16 + rc4];
#pragma unroll
            for (int ww = 1; ww < 8; ww++) {
                float4 p = pw4[((ww << 4) + rb) * 16 + rc4];
                s.x += p.x; s.y += p.y; s.z += p.z; s.w += p.w;
            }
            *(float4*)&gacc[rb * WTP + (rc4 << 2)] = s;
        }
        __syncthreads();

        // ---- gate fuse + state update ----
        {
            float gi = gacc[ub * WTP +  0 + un] + xgi;
            float gf = gacc[ub * WTP + 16 + un] + xgf;
            float gg = gacc[ub * WTP + 32 + un] + xgg;
            float go = gacc[ub * WTP + 48 + un] + xgo;

            float si = 1.f / (1.f + __expf(-gi));
            float sf = 1.f / (1.f + __expf(-gf));
            float so = 1.f / (1.f + __expf(-go));
            float cn = sf * c_reg + si * tanhf(gg);
            float hn = so * tanhf(cn);
            c_reg = cn;

            g_hbuf[cur ^ 1][b_glob * HH + n_base + un] = hn;
            out[((size_t)b_glob * TT + t) * HH + n_base + un] = hn;
        }

        grid_sync();
        cur ^= 1;
    }
}

// ============================================================
// Host launcher: 6 graph nodes total.
// ============================================================
extern "C" void kernel_launch(void* const* d_in, const int* in_sizes, int n_in,
                              void* d_out, int out_size)
{
    const float* x    = (const float*)d_in[0];
    const float* w_ih = (const float*)d_in[1];
    const float* w_hh = (const float*)d_in[2];
    const float* b_ih = (const float*)d_in[3];
    const float* b_hh = (const float*)d_in[4];
    float* out = (float*)d_out;

    float *bufA = nullptr, *bufB = nullptr;
    cudaGetSymbolAddress((void**)&bufA, g_bufA);
    cudaGetSymbolAddress((void**)&bufB, g_bufB);

    static bool attr_set = false;
    if (!attr_set) {
        cudaFuncSetAttribute(rec_persist,
                             cudaFuncAttributeMaxDynamicSharedMemorySize,
                             SMEM_FLOATS * sizeof(float));
        attr_set = true;
    }

    dim3 ggrid(512, 16);  // M/128, N/128
    for (int l = 0; l < 3; l++) {
        const float* in  = (l == 0) ? x    : (l == 1 ? bufA : bufB);
        float*       lo  = (l == 0) ? bufA : (l == 1 ? bufB : out);
        const float* Wih = w_ih + (size_t)l * G4 * HH;
        const float* Whh = w_hh + (size_t)l * G4 * HH;

        xg_gemm<<<ggrid, 256>>>(in, Wih, b_ih + l * G4, b_hh + l * G4);
        rec_persist<<<NCTA, 256, SMEM_FLOATS * sizeof(float)>>>(Whh, lo);
    }
}

// round 5
// speedup vs baseline: 1.9422x; 1.2564x over previous
#include <cuda_runtime.h>
#include <cuda_bf16.h>
#include <math.h>
#include <stdint.h>

#define BB   64
#define TT   1024
#define HH   512
#define G4   2048        // 4*H
#define MTOT (BB * TT)   // 65536

// ---- static device scratch (no allocation allowed) ----
__device__ float g_xg[(size_t)MTOT * G4];     // 512 MB: per-layer input projection
__device__ float g_bufA[(size_t)MTOT * HH];   // 128 MB: layer 0 output
__device__ float g_bufB[(size_t)MTOT * HH];   // 128 MB: layer 1 output
__device__ float g_hbuf[2][BB * HH];          // ping-pong hidden state
__device__ unsigned g_cnt = 0;                // grid barrier arrive counter
__device__ unsigned g_gen = 0;                // grid barrier generation

// bf16 split operands for the tensor-core input projection
__device__ __nv_bfloat16 g_xh[(size_t)MTOT * HH];  // 64 MB
__device__ __nv_bfloat16 g_xl[(size_t)MTOT * HH];  // 64 MB
__device__ __nv_bfloat16 g_wh[(size_t)G4 * HH];    // 2 MB
__device__ __nv_bfloat16 g_wl[(size_t)G4 * HH];    // 2 MB

// ============================================================
// small PTX helpers (all base-sm_103-safe: no 'a'-suffix features)
// ============================================================
__device__ __forceinline__ uint32_t smem_u32(const void* p) {
    uint32_t a;
    asm("{ .reg .u64 t; cvta.to.shared.u64 t, %1; cvt.u32.u64 %0, t; }"
        : "=r"(a) : "l"(p));
    return a;
}
__device__ __forceinline__ void ldsm4(uint32_t* r, uint32_t addr) {
    asm volatile("ldmatrix.sync.aligned.m8n8.x4.shared.b16 {%0,%1,%2,%3}, [%4];"
        : "=r"(r[0]), "=r"(r[1]), "=r"(r[2]), "=r"(r[3]) : "r"(addr));
}
__device__ __forceinline__ void mma_bf16(float* d, const uint32_t* a, const uint32_t* b) {
    asm volatile(
        "mma.sync.aligned.m16n8k16.row.col.f32.bf16.bf16.f32 "
        "{%0,%1,%2,%3}, {%4,%5,%6,%7}, {%8,%9}, {%0,%1,%2,%3};"
        : "+f"(d[0]), "+f"(d[1]), "+f"(d[2]), "+f"(d[3])
        : "r"(a[0]), "r"(a[1]), "r"(a[2]), "r"(a[3]), "r"(b[0]), "r"(b[1]));
}
__device__ __forceinline__ void cpa16(uint32_t smaddr, const void* g) {
    asm volatile("cp.async.cg.shared.global [%0], [%1], 16;" :: "r"(smaddr), "l"(g));
}
#define CPA_COMMIT() asm volatile("cp.async.commit_group;" ::: "memory")
#define CPA_WAIT0()  asm volatile("cp.async.wait_group 0;" ::: "memory")

__device__ __forceinline__ void fma2(unsigned long long& d, unsigned long long a,
                                     unsigned long long b) {
    asm("fma.rn.f32x2 %0, %1, %2, %0;" : "+l"(d) : "l"(a), "l"(b));
}

// ============================================================
// fp32 -> bf16 hi/lo split
// ============================================================
__global__ __launch_bounds__(256) void split_bf16(const float* __restrict__ in,
                                                  __nv_bfloat16* __restrict__ hi,
                                                  __nv_bfloat16* __restrict__ lo)
{
    int i = blockIdx.x * 256 + threadIdx.x;
    float v = in[i];
    __nv_bfloat16 h = __float2bfloat16_rn(v);
    hi[i] = h;
    lo[i] = __float2bfloat16_rn(v - __bfloat162float(h));
}

// ============================================================
// Input projection via mma.sync bf16 (3-pass hi/lo split):
//   g_xg[m,n] = sum_k x[m,k]*Wih[n,k] + bih[n] + bhh[n]
// CTA 128x128 tile, K chunks of 32 (double buffered, cp.async).
// 8 warps = 2(M) x 4(N); warp tile 64x32 = 4 m-atoms x 4 n-atoms.
// grid (16 n-tiles, 512 m-tiles) x 256 threads.
// ============================================================
#define AP       40                     // smem pitch in bf16 (80 B, bank-safe)
#define ARR_BF16 (128 * AP)             // 5120 bf16 per array
#define XG2_BIAS (8 * ARR_BF16 * 2)     // byte offset of bias (81920)
#define XG2_SMEM (XG2_BIAS + 512 + 16)

__global__ __launch_bounds__(256) void xg_mma2(const float* __restrict__ bih,
                                               const float* __restrict__ bhh)
{
    extern __shared__ __align__(16) char sm2[];
    __nv_bfloat16* tiles = (__nv_bfloat16*)sm2;       // [2 buf][4 arr][128*40]
    float* bias_sm = (float*)(sm2 + XG2_BIAS);
    const uint32_t smb = smem_u32(sm2);

    const int tid  = threadIdx.x;
    const int wid  = tid >> 5;
    const int lane = tid & 31;
    const int n_blk = blockIdx.x * 128;
    const int m_blk = blockIdx.y * 128;
    const int wm = wid & 1;          // m half (64)
    const int wn = wid >> 1;         // n quarter (32)

    if (tid < 128)
        bias_sm[tid] = __ldg(bih + n_blk + tid) + __ldg(bhh + n_blk + tid);

    const __nv_bfloat16* src[4] = {
        g_xh + (size_t)m_blk * HH, g_xl + (size_t)m_blk * HH,
        g_wh + (size_t)n_blk * HH, g_wl + (size_t)n_blk * HH };

    // issue cp.async for one 32-k chunk into buffer `buf`
    auto load_chunk = [&](int buf, int kc) {
#pragma unroll
        for (int a = 0; a < 4; a++) {
#pragma unroll
            for (int r = 0; r < 2; r++) {
                int unit = tid + r * 256;          // 0..511
                int row  = unit >> 2;
                int u    = unit & 3;
                uint32_t dst = smb +
                    (uint32_t)(((buf * 4 + a) * ARR_BF16 + row * AP + u * 8) * 2);
                cpa16(dst, src[a] + (size_t)row * HH + kc * 32 + u * 8);
            }
        }
    };

    float acc[4][4][4];
#pragma unroll
    for (int i = 0; i < 4; i++)
#pragma unroll
        for (int j = 0; j < 4; j++)
#pragma unroll
            for (int q = 0; q < 4; q++) acc[i][j][q] = 0.f;

    load_chunk(0, 0);
    CPA_COMMIT();

    // fragment address components
    const int arow  = lane & 15;
    const int asel  = (lane >> 4) << 3;          // k half select for A
    const int brow  = (lane & 7) + ((lane >> 4) << 3);
    const int bsel  = ((lane >> 3) & 1) << 3;    // k half select for B

    for (int c = 0; c < 16; c++) {
        CPA_WAIT0();
        __syncthreads();
        if (c < 15) { load_chunk((c + 1) & 1, c + 1); CPA_COMMIT(); }

        const uint32_t bufb = smb + (uint32_t)((c & 1) * 4 * ARR_BF16 * 2);
        const uint32_t ah = bufb;
        const uint32_t al = bufb + ARR_BF16 * 2;
        const uint32_t bh = bufb + 2 * ARR_BF16 * 2;
        const uint32_t bl = bufb + 3 * ARR_BF16 * 2;

#pragma unroll
        for (int k16 = 0; k16 < 2; k16++) {
            const int ka = k16 * 16 + asel;
            const int kb = k16 * 16 + bsel;
            uint32_t fah[4][4], fal[4][4], fbh[2][4], fbl[2][4];
#pragma unroll
            for (int ma = 0; ma < 4; ma++) {
                uint32_t off = (uint32_t)(((wm * 64 + ma * 16 + arow) * AP + ka) * 2);
                ldsm4(fah[ma], ah + off);
                ldsm4(fal[ma], al + off);
            }
#pragma unroll
            for (int nb = 0; nb < 2; nb++) {
                uint32_t off = (uint32_t)(((wn * 32 + nb * 16 + brow) * AP + kb) * 2);
                ldsm4(fbh[nb], bh + off);
                ldsm4(fbl[nb], bl + off);
            }
#pragma unroll
            for (int ma = 0; ma < 4; ma++) {
#pragma unroll
                for (int n = 0; n < 4; n++) {
                    const uint32_t* bhf = &fbh[n >> 1][(n & 1) * 2];
                    const uint32_t* blf = &fbl[n >> 1][(n & 1) * 2];
                    mma_bf16(acc[ma][n], fah[ma], bhf);
                    mma_bf16(acc[ma][n], fah[ma], blf);
                    mma_bf16(acc[ma][n], fal[ma], bhf);
                }
            }
        }
    }
    __syncthreads();

    // epilogue: d0,d1 -> (row, col:col+1), d2,d3 -> (row+8, col:col+1)
    const int r = lane >> 2;
    const int q = lane & 3;
#pragma unroll
    for (int ma = 0; ma < 4; ma++) {
#pragma unroll
        for (int n = 0; n < 4; n++) {
            int m   = m_blk + wm * 64 + ma * 16 + r;
            int col = wn * 32 + n * 8 + q * 2;       // local col in [0,128)
            float b0 = bias_sm[col], b1 = bias_sm[col + 1];
            float2 v0, v1;
            v0.x = acc[ma][n][0] + b0; v0.y = acc[ma][n][1] + b1;
            v1.x = acc[ma][n][2] + b0; v1.y = acc[ma][n][3] + b1;
            *(float2*)(g_xg + (size_t)m * G4 + n_blk + col)       = v0;
            *(float2*)(g_xg + (size_t)(m + 8) * G4 + n_blk + col) = v1;
        }
    }
}

// ============================================================
// Persistent recurrence kernel, f32x2 edition.
// 128 CTAs x 256 threads, co-resident. CTA: 16 batch x 16 hidden (64 gate
// cols). Weights in smem as k-pair-major ull: wp[k2][jj], jj = gate*16+n.
// Warp w owns k-chunk [w*64, w*64+64); lane: c4 = hidden n (0..15),
// bg = batch group; acc2[8 batches][4 gates] packed f32x2 over (k even, odd).
// ============================================================
#define HSP  520
#define NCTA 128
#define WP_OFF  0                        // 256*64 ull = 32768 floats
#define HS_OFF  32768                    // 16*520 + 8 = 8328 floats
#define PW_OFF  (HS_OFF + 8328)          // 8192 floats
#define GA_OFF  (PW_OFF + 8192)          // 16*68 = 1088 floats
#define REC_SMEM_FLOATS (GA_OFF + 1088)

__device__ __forceinline__ void grid_sync()
{
    __syncthreads();
    if (threadIdx.x == 0) {
        __threadfence();
        unsigned my = *(volatile unsigned*)&g_gen;
        if (atomicAdd(&g_cnt, 1) == NCTA - 1) {
            atomicExch(&g_cnt, 0);
            __threadfence();
            atomicAdd(&g_gen, 1);
        } else {
            while (*(volatile unsigned*)&g_gen == my) { }
        }
        __threadfence();
    }
    __syncthreads();
}

__global__ __launch_bounds__(256, 1) void rec_persist(const float* __restrict__ Whh,
                                                      float* __restrict__ out)
{
    extern __shared__ float smf[];
    unsigned long long* wp = (unsigned long long*)(smf + WP_OFF); // [k2][64]
    float* h_s  = smf + HS_OFF;                                   // [b][k] +skew
    float* pw   = smf + PW_OFF;                                   // [w][16][64]
    float* gacc = smf + GA_OFF;                                   // [b][68]

    const int tid    = threadIdx.x;
    const int cta    = blockIdx.x;
    const int b_base = (cta >> 5) << 4;
    const int n_base = (cta & 31) << 4;

    // ---- load weights as k-pairs: wp[k2*64 + jj] = (W[j][2k2], W[j][2k2+1]) ----
    for (int e = tid; e < 64 * 256; e += 256) {
        int jj = e >> 8;            // 0..63  (gate*16 + n)
        int k2 = e & 255;
        int jglob = ((jj >> 4) << 9) + n_base + (jj & 15);
        wp[k2 * 64 + jj] =
            *(const unsigned long long*)(Whh + (size_t)jglob * HH + k2 * 2);
    }
    g_hbuf[0][cta * 256 + tid] = 0.f;

    // GEMM-role indices
    const int w    = tid >> 5;        // k chunk [w*64, w*64+64) -> pairs kc2=w*32
    const int lane = tid & 31;
    const int c4   = lane & 15;       // hidden n
    const int bg   = lane >> 4;       // batch group
    const int bg8  = bg << 3;
    const int kc2  = w << 5;

    // gate-role indices
    const int ub = tid >> 4;
    const int un = tid & 15;
    const int b_glob = b_base + ub;
    float c_reg = 0.f;

    // reduce-role
    const int rb  = tid >> 4;
    const int rc4 = tid & 15;

    grid_sync();

    int cur = 0;
    for (int t = 0; t < TT; t++) {
        // prefetch xg gate pre-activations
        const float* xr = g_xg + ((size_t)b_glob * TT + t) * G4 + n_base + un;
        float xgi = __ldg(xr);
        float xgf = __ldg(xr + 512);
        float xgg = __ldg(xr + 1024);
        float xgo = __ldg(xr + 1536);

        // stage h tile [16 x 512] into smem (bg-skewed)
        const float* hc = g_hbuf[cur] + (size_t)b_base * HH;
        for (int idx = tid; idx < 16 * 128; idx += 256) {
            int b  = idx >> 7;
            int k4 = idx & 127;
            float4 v = *(const float4*)(hc + b * HH + (k4 << 2));
            *(float4*)&h_s[b * HSP + ((b >> 3) << 3) + (k4 << 2)] = v;
        }
        __syncthreads();

        // ---- packed GEMM: acc2[i][c] over this warp's 32 k-pairs ----
        unsigned long long acc2[8][4];
#pragma unroll
        for (int i = 0; i < 8; i++)
#pragma unroll
            for (int c = 0; c < 4; c++) acc2[i][c] = 0ULL;

        const unsigned long long* wrow = wp + (size_t)kc2 * 64 + c4;
        const float* hrow = h_s + (size_t)bg8 * HSP + (bg << 3) + (kc2 << 1);

#pragma unroll 2
        for (int kk2 = 0; kk2 < 32; kk2 += 2) {
            unsigned long long wv0[4], wv1[4];
#pragma unroll
            for (int c = 0; c < 4; c++) {
                wv0[c] = wrow[(kk2 + 0) * 64 + c * 16];
                wv1[c] = wrow[(kk2 + 1) * 64 + c * 16];
            }
#pragma unroll
            for (int i = 0; i < 8; i++) {
                ulonglong2 hv = *(const ulonglong2*)(hrow + i * HSP + (kk2 << 1));
#pragma unroll
                for (int c = 0; c < 4; c++) {
                    fma2(acc2[i][c], hv.x, wv0[c]);
                    fma2(acc2[i][c], hv.y, wv1[c]);
                }
            }
        }

        // collapse pairs, store per-warp partials: pw[w][b][jj], jj = c*16+c4
#pragma unroll
        for (int i = 0; i < 8; i++) {
#pragma unroll
            for (int c = 0; c < 4; c++) {
                float2 f = *reinterpret_cast<float2*>(&acc2[i][c]);
                pw[((w << 4) + bg8 + i) * 64 + c * 16 + c4] = f.x + f.y;
            }
        }
        __syncthreads();

        // reduce 8 warp-partials -> gacc[b][jj] (pitch 68)
        {
            float4 s = *(const float4*)(pw + rb * 64 + (rc4 << 2));
#pragma unroll
            for (int ww = 1; ww < 8; ww++) {
                float4 p = *(const float4*)(pw + ((ww << 4) + rb) * 64 + (rc4 << 2));
                s.x += p.x; s.y += p.y; s.z += p.z; s.w += p.w;
            }
            *(float4*)&gacc[rb * 68 + (rc4 << 2)] = s;
        }
        __syncthreads();

        // gate fuse + state update
        {
            float gi = gacc[ub * 68 +  0 + un] + xgi;
            float gf = gacc[ub * 68 + 16 + un] + xgf;
            float gg = gacc[ub * 68 + 32 + un] + xgg;
            float go = gacc[ub * 68 + 48 + un] + xgo;

            float si = 1.f / (1.f + __expf(-gi));
            float sf = 1.f / (1.f + __expf(-gf));
            float so = 1.f / (1.f + __expf(-go));
            float cn = sf * c_reg + si * tanhf(gg);
            float hn = so * tanhf(cn);
            c_reg = cn;

            g_hbuf[cur ^ 1][b_glob * HH + n_base + un] = hn;
            out[((size_t)b_glob * TT + t) * HH + n_base + un] = hn;
        }

        grid_sync();
        cur ^= 1;
    }
}

// ============================================================
// Host launcher: 12 graph nodes total.
// ============================================================
extern "C" void kernel_launch(void* const* d_in, const int* in_sizes, int n_in,
                              void* d_out, int out_size)
{
    const float* x    = (const float*)d_in[0];
    const float* w_ih = (const float*)d_in[1];
    const float* w_hh = (const float*)d_in[2];
    const float* b_ih = (const float*)d_in[3];
    const float* b_hh = (const float*)d_in[4];
    float* out = (float*)d_out;

    float *bufA = nullptr, *bufB = nullptr;
    __nv_bfloat16 *xh, *xl, *wh, *wl;
    cudaGetSymbolAddress((void**)&bufA, g_bufA);
    cudaGetSymbolAddress((void**)&bufB, g_bufB);
    cudaGetSymbolAddress((void**)&xh, g_xh);
    cudaGetSymbolAddress((void**)&xl, g_xl);
    cudaGetSymbolAddress((void**)&wh, g_wh);
    cudaGetSymbolAddress((void**)&wl, g_wl);

    static bool attr_set = false;
    if (!attr_set) {
        cudaFuncSetAttribute(rec_persist,
                             cudaFuncAttributeMaxDynamicSharedMemorySize,
                             REC_SMEM_FLOATS * sizeof(float));
        cudaFuncSetAttribute(xg_mma2,
                             cudaFuncAttributeMaxDynamicSharedMemorySize,
                             XG2_SMEM);
        attr_set = true;
    }

    dim3 mgrid(16, 512);   // n-tiles x m-tiles
    for (int l = 0; l < 3; l++) {
        const float* in  = (l == 0) ? x    : (l == 1 ? bufA : bufB);
        float*       lo  = (l == 0) ? bufA : (l == 1 ? bufB : out);
        const float* Wih = w_ih + (size_t)l * G4 * HH;
        const float* Whh = w_hh + (size_t)l * G4 * HH;

        split_bf16<<<(MTOT * HH) / 256, 256>>>(in, xh, xl);
        split_bf16<<<(G4 * HH) / 256, 256>>>(Wih, wh, wl);
        xg_mma2<<<mgrid, 256, XG2_SMEM>>>(b_ih + l * G4, b_hh + l * G4);
        rec_persist<<<NCTA, 256, REC_SMEM_FLOATS * sizeof(float)>>>(Whh, lo);
    }
}

// round 6
// speedup vs baseline: 2.5737x; 1.3251x over previous
#include <cuda_runtime.h>
#include <cuda_bf16.h>
#include <math.h>
#include <stdint.h>

#define BB   64
#define TT   1024
#define HH   512
#define G4   2048        // 4*H
#define MTOT (BB * TT)   // 65536

// ---- static device scratch (no allocation allowed) ----
__device__ float g_xg[(size_t)MTOT * G4];     // 512 MB: per-layer input projection
__device__ float g_bufA[(size_t)MTOT * HH];   // 128 MB: layer 0 output
__device__ float g_bufB[(size_t)MTOT * HH];   // 128 MB: layer 1 output
__device__ uint32_t g_hpack[2][BB * HH];      // ping-pong h as packed (bf16 hi | lo<<16)
__device__ unsigned g_cnt = 0;                // grid barrier arrive counter
__device__ unsigned g_gen = 0;                // grid barrier generation

// bf16 split operands for the tensor-core input projection
__device__ __nv_bfloat16 g_xh[(size_t)MTOT * HH];  // 64 MB
__device__ __nv_bfloat16 g_xl[(size_t)MTOT * HH];  // 64 MB
__device__ __nv_bfloat16 g_wh[(size_t)G4 * HH];    // 2 MB
__device__ __nv_bfloat16 g_wl[(size_t)G4 * HH];    // 2 MB

// ============================================================
// small PTX helpers (all base-sm_103-safe: no 'a'-suffix features)
// ============================================================
__device__ __forceinline__ uint32_t smem_u32(const void* p) {
    uint32_t a;
    asm("{ .reg .u64 t; cvta.to.shared.u64 t, %1; cvt.u32.u64 %0, t; }"
        : "=r"(a) : "l"(p));
    return a;
}
__device__ __forceinline__ void ldsm4(uint32_t* r, uint32_t addr) {
    asm volatile("ldmatrix.sync.aligned.m8n8.x4.shared.b16 {%0,%1,%2,%3}, [%4];"
        : "=r"(r[0]), "=r"(r[1]), "=r"(r[2]), "=r"(r[3]) : "r"(addr));
}
__device__ __forceinline__ void mma_bf16(float* d, const uint32_t* a, const uint32_t* b) {
    asm volatile(
        "mma.sync.aligned.m16n8k16.row.col.f32.bf16.bf16.f32 "
        "{%0,%1,%2,%3}, {%4,%5,%6,%7}, {%8,%9}, {%0,%1,%2,%3};"
        : "+f"(d[0]), "+f"(d[1]), "+f"(d[2]), "+f"(d[3])
        : "r"(a[0]), "r"(a[1]), "r"(a[2]), "r"(a[3]), "r"(b[0]), "r"(b[1]));
}
__device__ __forceinline__ void cpa16(uint32_t smaddr, const void* g) {
    asm volatile("cp.async.cg.shared.global [%0], [%1], 16;" :: "r"(smaddr), "l"(g));
}
#define CPA_COMMIT() asm volatile("cp.async.commit_group;" ::: "memory")
#define CPA_WAIT0()  asm volatile("cp.async.wait_group 0;" ::: "memory")

// ============================================================
// fp32 -> bf16 hi/lo split
// ============================================================
__global__ __launch_bounds__(256) void split_bf16(const float* __restrict__ in,
                                                  __nv_bfloat16* __restrict__ hi,
                                                  __nv_bfloat16* __restrict__ lo)
{
    int i = blockIdx.x * 256 + threadIdx.x;
    float v = in[i];
    __nv_bfloat16 h = __float2bfloat16_rn(v);
    hi[i] = h;
    lo[i] = __float2bfloat16_rn(v - __bfloat162float(h));
}

// ============================================================
// Input projection via mma.sync bf16 (3-pass hi/lo split)  [unchanged]
// ============================================================
#define AP       40
#define ARR_BF16 (128 * AP)
#define XG2_BIAS (8 * ARR_BF16 * 2)
#define XG2_SMEM (XG2_BIAS + 512 + 16)

__global__ __launch_bounds__(256) void xg_mma2(const float* __restrict__ bih,
                                               const float* __restrict__ bhh)
{
    extern __shared__ __align__(16) char sm2[];
    float* bias_sm = (float*)(sm2 + XG2_BIAS);
    const uint32_t smb = smem_u32(sm2);

    const int tid  = threadIdx.x;
    const int wid  = tid >> 5;
    const int lane = tid & 31;
    const int n_blk = blockIdx.x * 128;
    const int m_blk = blockIdx.y * 128;
    const int wm = wid & 1;
    const int wn = wid >> 1;

    if (tid < 128)
        bias_sm[tid] = __ldg(bih + n_blk + tid) + __ldg(bhh + n_blk + tid);

    const __nv_bfloat16* src[4] = {
        g_xh + (size_t)m_blk * HH, g_xl + (size_t)m_blk * HH,
        g_wh + (size_t)n_blk * HH, g_wl + (size_t)n_blk * HH };

    auto load_chunk = [&](int buf, int kc) {
#pragma unroll
        for (int a = 0; a < 4; a++) {
#pragma unroll
            for (int r = 0; r < 2; r++) {
                int unit = tid + r * 256;
                int row  = unit >> 2;
                int u    = unit & 3;
                uint32_t dst = smb +
                    (uint32_t)(((buf * 4 + a) * ARR_BF16 + row * AP + u * 8) * 2);
                cpa16(dst, src[a] + (size_t)row * HH + kc * 32 + u * 8);
            }
        }
    };

    float acc[4][4][4];
#pragma unroll
    for (int i = 0; i < 4; i++)
#pragma unroll
        for (int j = 0; j < 4; j++)
#pragma unroll
            for (int q = 0; q < 4; q++) acc[i][j][q] = 0.f;

    load_chunk(0, 0);
    CPA_COMMIT();

    const int arow  = lane & 15;
    const int asel  = (lane >> 4) << 3;
    const int brow  = (lane & 7) + ((lane >> 4) << 3);
    const int bsel  = ((lane >> 3) & 1) << 3;

    for (int c = 0; c < 16; c++) {
        CPA_WAIT0();
        __syncthreads();
        if (c < 15) { load_chunk((c + 1) & 1, c + 1); CPA_COMMIT(); }

        const uint32_t bufb = smb + (uint32_t)((c & 1) * 4 * ARR_BF16 * 2);
        const uint32_t ah = bufb;
        const uint32_t al = bufb + ARR_BF16 * 2;
        const uint32_t bh = bufb + 2 * ARR_BF16 * 2;
        const uint32_t bl = bufb + 3 * ARR_BF16 * 2;

#pragma unroll
        for (int k16 = 0; k16 < 2; k16++) {
            const int ka = k16 * 16 + asel;
            const int kb = k16 * 16 + bsel;
            uint32_t fah[4][4], fal[4][4], fbh[2][4], fbl[2][4];
#pragma unroll
            for (int ma = 0; ma < 4; ma++) {
                uint32_t off = (uint32_t)(((wm * 64 + ma * 16 + arow) * AP + ka) * 2);
                ldsm4(fah[ma], ah + off);
                ldsm4(fal[ma], al + off);
            }
#pragma unroll
            for (int nb = 0; nb < 2; nb++) {
                uint32_t off = (uint32_t)(((wn * 32 + nb * 16 + brow) * AP + kb) * 2);
                ldsm4(fbh[nb], bh + off);
                ldsm4(fbl[nb], bl + off);
            }
#pragma unroll
            for (int ma = 0; ma < 4; ma++) {
#pragma unroll
                for (int n = 0; n < 4; n++) {
                    const uint32_t* bhf = &fbh[n >> 1][(n & 1) * 2];
                    const uint32_t* blf = &fbl[n >> 1][(n & 1) * 2];
                    mma_bf16(acc[ma][n], fah[ma], bhf);
                    mma_bf16(acc[ma][n], fah[ma], blf);
                    mma_bf16(acc[ma][n], fal[ma], bhf);
                }
            }
        }
    }
    __syncthreads();

    const int r = lane >> 2;
    const int q = lane & 3;
#pragma unroll
    for (int ma = 0; ma < 4; ma++) {
#pragma unroll
        for (int n = 0; n < 4; n++) {
            int m   = m_blk + wm * 64 + ma * 16 + r;
            int col = wn * 32 + n * 8 + q * 2;
            float b0 = bias_sm[col], b1 = bias_sm[col + 1];
            float2 v0, v1;
            v0.x = acc[ma][n][0] + b0; v0.y = acc[ma][n][1] + b1;
            v1.x = acc[ma][n][2] + b0; v1.y = acc[ma][n][3] + b1;
            *(float2*)(g_xg + (size_t)m * G4 + n_blk + col)       = v0;
            *(float2*)(g_xg + (size_t)(m + 8) * G4 + n_blk + col) = v1;
        }
    }
}

// ============================================================
// Persistent recurrence kernel — TENSOR CORE edition.
// 128 CTAs x 256 threads, co-resident. CTA: 16 batch x 16 hidden
// (64 gate cols jj = gate*16+n). K=512 split across 8 warps (64 k each).
// Weights resident in smem as bf16 hi/lo [jj][k] (pitch 520 bf16).
// h carried between steps as packed (hi|lo<<16) uint32 in global memory;
// staged per step into smem bf16 hi/lo [b][k]. 3-pass bf16 mma.sync,
// fp32 partials, 8-way smem reduce, fused gates.
// ============================================================
#define HP   520                         // bf16 pitch (1040 B; 65 16B-units, coprime 8)
#define NCTA 128

// byte offsets into dynamic smem
#define WH_OFF   0
#define WL_OFF   66560                   // 64*520*2
#define HH_OFF   133120
#define HL_OFF   149760                  // +16*520*2
#define PW_OFF   166400                  // +16*520*2
#define GA_OFF   201216                  // +128*68*4 = 34816
#define REC_SMEM 205568                  // +16*68*4  = 4352

__device__ __forceinline__ void grid_sync()
{
    __syncthreads();
    if (threadIdx.x == 0) {
        __threadfence();
        unsigned my = *(volatile unsigned*)&g_gen;
        if (atomicAdd(&g_cnt, 1) == NCTA - 1) {
            atomicExch(&g_cnt, 0);
            __threadfence();
            atomicAdd(&g_gen, 1);
        } else {
            while (*(volatile unsigned*)&g_gen == my) { }
        }
        __threadfence();
    }
    __syncthreads();
}

__global__ __launch_bounds__(256, 1) void rec_persist(const float* __restrict__ Whh,
                                                      float* __restrict__ out)
{
    extern __shared__ __align__(16) char smc[];
    __nv_bfloat16* wh_s = (__nv_bfloat16*)(smc + WH_OFF);   // [jj][k] pitch HP
    __nv_bfloat16* wl_s = (__nv_bfloat16*)(smc + WL_OFF);
    __nv_bfloat16* hh_s = (__nv_bfloat16*)(smc + HH_OFF);   // [b][k] pitch HP
    __nv_bfloat16* hl_s = (__nv_bfloat16*)(smc + HL_OFF);
    float* pw   = (float*)(smc + PW_OFF);                   // [w*16+b][68]
    float* gacc = (float*)(smc + GA_OFF);                   // [b][68]
    const uint32_t smb = smem_u32(smc);

    const int tid    = threadIdx.x;
    const int cta    = blockIdx.x;
    const int b_base = (cta >> 5) << 4;
    const int n_base = (cta & 31) << 4;

    // ---- load + split weight tile once: jj = gate*16 + n, k = 0..511 ----
    for (int e = tid; e < 64 * 512; e += 256) {
        int jj = e >> 9;
        int k  = e & 511;
        int jglob = ((jj >> 4) << 9) + n_base + (jj & 15);
        float v = Whh[(size_t)jglob * HH + k];
        __nv_bfloat16 h = __float2bfloat16_rn(v);
        wh_s[jj * HP + k] = h;
        wl_s[jj * HP + k] = __float2bfloat16_rn(v - __bfloat162float(h));
    }
    g_hpack[0][cta * 256 + tid] = 0u;     // zero initial h

    // role indices
    const int w    = tid >> 5;            // warp: k chunk [w*64, w*64+64)
    const int lane = tid & 31;
    const int kbase = w << 6;
    const int arow = lane & 15;
    const int asel = (lane >> 4) << 3;
    const int brow = (lane & 7) + ((lane >> 4) << 3);
    const int bsel = ((lane >> 3) & 1) << 3;
    const int dr   = lane >> 2;           // D row within m16
    const int dq   = lane & 3;            // D col pair

    const int ub = tid >> 4;              // gate-role: batch
    const int un = tid & 15;              // gate-role: hidden n
    const int b_glob = b_base + ub;
    float c_reg = 0.f;

    const int rb  = tid >> 4;             // reduce-role
    const int rc4 = tid & 15;

    grid_sync();

    int cur = 0;
    for (int t = 0; t < TT; t++) {
        // ---- prefetch xg gate pre-activations (global, L2) ----
        const float* xr = g_xg + ((size_t)b_glob * TT + t) * G4 + n_base + un;
        float xgi = __ldg(xr);
        float xgf = __ldg(xr + 512);
        float xgg = __ldg(xr + 1024);
        float xgo = __ldg(xr + 1536);

        // ---- stage h tile [16 x 512] packed -> smem bf16 hi/lo ----
        const uint32_t* hc = g_hpack[cur] + (size_t)b_base * HH;
        for (int idx = tid; idx < 16 * 128; idx += 256) {
            int b  = idx >> 7;
            int k4 = idx & 127;
            uint4 u = *(const uint4*)(hc + b * HH + (k4 << 2));
            uint2 hh, hl;
            hh.x = (u.x & 0xFFFFu) | (u.y << 16);
            hh.y = (u.z & 0xFFFFu) | (u.w << 16);
            hl.x = (u.x >> 16) | (u.y & 0xFFFF0000u);
            hl.y = (u.z >> 16) | (u.w & 0xFFFF0000u);
            *(uint2*)&hh_s[b * HP + (k4 << 2)] = hh;
            *(uint2*)&hl_s[b * HP + (k4 << 2)] = hl;
        }
        __syncthreads();

        // ---- tensor-core k-chunk GEMM: [16 x 64k] x [64k x 64jj] ----
        float acc[8][4];
#pragma unroll
        for (int i = 0; i < 8; i++)
#pragma unroll
            for (int j = 0; j < 4; j++) acc[i][j] = 0.f;

        uint32_t fah[4][4], fal[4][4];
#pragma unroll
        for (int k16 = 0; k16 < 4; k16++) {
            uint32_t off = (uint32_t)((arow * HP + kbase + k16 * 16 + asel) * 2);
            ldsm4(fah[k16], smb + HH_OFF + off);
            ldsm4(fal[k16], smb + HL_OFF + off);
        }
#pragma unroll
        for (int k16 = 0; k16 < 4; k16++) {
#pragma unroll
            for (int nb = 0; nb < 4; nb++) {
                uint32_t off = (uint32_t)(((nb * 16 + brow) * HP +
                                           kbase + k16 * 16 + bsel) * 2);
                uint32_t bh[4], bl[4];
                ldsm4(bh, smb + WH_OFF + off);
                ldsm4(bl, smb + WL_OFF + off);
                mma_bf16(acc[2 * nb + 0], fah[k16], bh + 0);
                mma_bf16(acc[2 * nb + 1], fah[k16], bh + 2);
                mma_bf16(acc[2 * nb + 0], fah[k16], bl + 0);
                mma_bf16(acc[2 * nb + 1], fah[k16], bl + 2);
                mma_bf16(acc[2 * nb + 0], fal[k16], bh + 0);
                mma_bf16(acc[2 * nb + 1], fal[k16], bh + 2);
            }
        }

        // ---- store per-warp partials: pw[w*16 + b][jj] (pitch 68) ----
#pragma unroll
        for (int na = 0; na < 8; na++) {
            int col = na * 8 + dq * 2;
            float2 v0, v1;
            v0.x = acc[na][0]; v0.y = acc[na][1];
            v1.x = acc[na][2]; v1.y = acc[na][3];
            *(float2*)(pw + ((w << 4) + dr) * 68 + col)     = v0;
            *(float2*)(pw + ((w << 4) + dr + 8) * 68 + col) = v1;
        }
        __syncthreads();

        // ---- reduce 8 warp-partials -> gacc[b][jj] ----
        {
            float4 s = *(const float4*)(pw + rb * 68 + (rc4 << 2));
#pragma unroll
            for (int ww = 1; ww < 8; ww++) {
                float4 p = *(const float4*)(pw + ((ww << 4) + rb) * 68 + (rc4 << 2));
                s.x += p.x; s.y += p.y; s.z += p.z; s.w += p.w;
            }
            *(float4*)&gacc[rb * 68 + (rc4 << 2)] = s;
        }
        __syncthreads();

        // ---- gate fuse + state update ----
        {
            float gi = gacc[ub * 68 +  0 + un] + xgi;
            float gf = gacc[ub * 68 + 16 + un] + xgf;
            float gg = gacc[ub * 68 + 32 + un] + xgg;
            float go = gacc[ub * 68 + 48 + un] + xgo;

            float si = 1.f / (1.f + __expf(-gi));
            float sf = 1.f / (1.f + __expf(-gf));
            float so = 1.f / (1.f + __expf(-go));
            float cn = sf * c_reg + si * tanhf(gg);
            float hn = so * tanhf(cn);
            c_reg = cn;

            __nv_bfloat16 hhi = __float2bfloat16_rn(hn);
            __nv_bfloat16 hlo = __float2bfloat16_rn(hn - __bfloat162float(hhi));
            uint32_t u = (uint32_t)__bfloat16_as_ushort(hhi) |
                         ((uint32_t)__bfloat16_as_ushort(hlo) << 16);
            g_hpack[cur ^ 1][b_glob * HH + n_base + un] = u;
            out[((size_t)b_glob * TT + t) * HH + n_base + un] = hn;
        }

        grid_sync();
        cur ^= 1;
    }
}

// ============================================================
// Host launcher: 12 graph nodes total.
// ============================================================
extern "C" void kernel_launch(void* const* d_in, const int* in_sizes, int n_in,
                              void* d_out, int out_size)
{
    const float* x    = (const float*)d_in[0];
    const float* w_ih = (const float*)d_in[1];
    const float* w_hh = (const float*)d_in[2];
    const float* b_ih = (const float*)d_in[3];
    const float* b_hh = (const float*)d_in[4];
    float* out = (float*)d_out;

    float *bufA = nullptr, *bufB = nullptr;
    __nv_bfloat16 *xh, *xl, *wh, *wl;
    cudaGetSymbolAddress((void**)&bufA, g_bufA);
    cudaGetSymbolAddress((void**)&bufB, g_bufB);
    cudaGetSymbolAddress((void**)&xh, g_xh);
    cudaGetSymbolAddress((void**)&xl, g_xl);
    cudaGetSymbolAddress((void**)&wh, g_wh);
    cudaGetSymbolAddress((void**)&wl, g_wl);

    static bool attr_set = false;
    if (!attr_set) {
        cudaFuncSetAttribute(rec_persist,
                             cudaFuncAttributeMaxDynamicSharedMemorySize, REC_SMEM);
        cudaFuncSetAttribute(xg_mma2,
                             cudaFuncAttributeMaxDynamicSharedMemorySize, XG2_SMEM);
        attr_set = true;
    }

    dim3 mgrid(16, 512);   // n-tiles x m-tiles
    for (int l = 0; l < 3; l++) {
        const float* in  = (l == 0) ? x    : (l == 1 ? bufA : bufB);
        float*       lo  = (l == 0) ? bufA : (l == 1 ? bufB : out);
        const float* Wih = w_ih + (size_t)l * G4 * HH;
        const float* Whh = w_hh + (size_t)l * G4 * HH;

        split_bf16<<<(MTOT * HH) / 256, 256>>>(in, xh, xl);
        split_bf16<<<(G4 * HH) / 256, 256>>>(Wih, wh, wl);
        xg_mma2<<<mgrid, 256, XG2_SMEM>>>(b_ih + l * G4, b_hh + l * G4);
        rec_persist<<<NCTA, 256, REC_SMEM>>>(Whh, lo);
    }
}